// round 14
// baseline (speedup 1.0000x reference)
#include <cuda_runtime.h>
#include <math.h>

#define BSZ 4096
#define HSZ 512
#define KSZ 32
#define DSZ 20
#define NPAIR 496   // 32*31/2
#define NBB 64
#define GRID 592    // 148 SMs x 4 co-resident blocks
#define TPB 256

typedef unsigned long long u64;

// ---------------- device scratch (no allocations allowed) ----------------
__device__ float  g_pm[NBB][HSZ][KSZ];   // partial class sums  [bb][h][k]
__device__ float  g_ps[NBB][HSZ][KSZ];   // partial sum h^2c^2  [bb][h][k]
__device__ double g_pcnt[NBB][KSZ];
__device__ float  g_m[KSZ][HSZ];
__device__ float  g_w[KSZ][HSZ];
__device__ float  g_tab_even[2048];      // c_j = (2j-1)!!/(2j)!!
__device__ float  g_tab_odd[2048];       // c_j = (2j)!!/(2j+1)!!

__device__ unsigned long long g_acc;     // fixed-point (2^-32) accumulator
__device__ unsigned int g_done;

__device__ unsigned int g_bar_count = 0;
__device__ volatile unsigned int g_bar_gen = 0;

__device__ __forceinline__ void grid_barrier() {
    __syncthreads();
    __threadfence();
    if (threadIdx.x == 0) {
        unsigned int gen = g_bar_gen;
        unsigned int t = atomicAdd(&g_bar_count, 1u);
        if (t == GRID - 1) {
            g_bar_count = 0u;
            __threadfence();
            g_bar_gen = gen + 1u;
        } else {
            while (g_bar_gen == gen) __nanosleep(64);
        }
    }
    __syncthreads();
    __threadfence();
}

__device__ __forceinline__ u64 ffma2(u64 a, u64 b, u64 c) {
    u64 d;
    asm("fma.rn.f32x2 %0, %1, %2, %3;" : "=l"(d) : "l"(a), "l"(b), "l"(c));
    return d;
}
__device__ __forceinline__ float f2lo(u64 v) { return __uint_as_float((unsigned)v); }
__device__ __forceinline__ float f2hi(u64 v) { return __uint_as_float((unsigned)(v >> 32)); }

union F4U { float4 f; u64 d[2]; };

// ln B(1/2, b) without lgamma (CF fallback path only).
__device__ __forceinline__ double lbeta_half(double b) {
    double z = b, prod = 1.0;
#pragma unroll 1
    while (z < 32.0) { prod *= z / (z + 0.5); z += 1.0; }
    double iz = 1.0 / z;
    double ser = 1.0 + iz * (-0.125 + iz * (0.0078125 +
                 iz * (0.0048828125 + iz * (-0.000640869140625))));
    return 0.57236494292470008707 - log(prod * sqrt(z) * ser);
}

// Per-thread Lentz CF (divergence-safe). Fallback only (non-integer nu).
__device__ __forceinline__ float betacf_thread(float a, float b, float x) {
    const float FPMIN = 1e-30f;
    float qab = a + b, qap = a + 1.0f, qam = a - 1.0f;
    float c = 1.0f;
    float d = 1.0f - qab * x / qap;
    if (fabsf(d) < FPMIN) d = FPMIN;
    d = 1.0f / d;
    float hh = d;
#pragma unroll 1
    for (int m = 1; m <= 200; m++) {
        float fm = (float)m, m2 = 2.0f * fm;
        float aa = fm * (b - fm) * x / ((qam + m2) * (a + m2));
        d = 1.0f + aa * d; if (fabsf(d) < FPMIN) d = FPMIN;
        c = 1.0f + aa / c; if (fabsf(c) < FPMIN) c = FPMIN;
        d = 1.0f / d;
        hh *= d * c;
        aa = -(a + fm) * (qab + fm) * x / ((a + m2) * (qap + m2));
        d = 1.0f + aa * d; if (fabsf(d) < FPMIN) d = FPMIN;
        c = 1.0f + aa / c; if (fabsf(c) < FPMIN) c = FPMIN;
        d = 1.0f / d;
        float del = d * c;
        hh *= del;
        if (fabsf(del - 1.0f) < 2.4e-7f) break;
    }
    return hh;
}

__device__ __forceinline__ void pair_ij(int p, int& ii, int& jj) {
    int i = 0, rem = p;
    while (rem >= (KSZ - 1 - i)) { rem -= (KSZ - 1 - i); i++; }
    ii = i; jj = i + 1 + rem;
}

// ====== K1: stats (grid (66,4)); bb 64/65 build coeff tables ==============
__global__ __launch_bounds__(TPB) void stats_kernel(const float* __restrict__ hidden,
                                                    const float* __restrict__ cluster) {
    __shared__ float sh_hidp[32][256];   // packed pairs {h, h^2}
    __shared__ float sh_cp[32][64];      // packed pairs {c, c^2}
    __shared__ double sh_cnt[TPB];

    const int tid = (int)threadIdx.x;
    const int bb = (int)blockIdx.x;
    const int hb = (int)blockIdx.y;

    if (bb >= NBB) {
        if (hb != 0) return;
        const int which = bb - NBB;      // 0 = even, 1 = odd
        __shared__ double sp[TPB];
        double prod = 1.0;
#pragma unroll
        for (int e = 0; e < 8; e++) {
            int j = tid * 8 + e;
            double ratio = 1.0;
            if (j > 0) ratio = which ? (double)(2 * j) / (double)(2 * j + 1)
                                     : (double)(2 * j - 1) / (double)(2 * j);
            prod *= ratio;
        }
        sp[tid] = prod;
        __syncthreads();
        for (int off = 1; off < TPB; off <<= 1) {
            double v = sp[tid];
            double u = (tid >= off) ? sp[tid - off] : 1.0;
            __syncthreads();
            sp[tid] = v * u;
            __syncthreads();
        }
        double run = (tid == 0) ? 1.0 : sp[tid - 1];
        float* tab = which ? g_tab_odd : g_tab_even;
#pragma unroll
        for (int e = 0; e < 8; e++) {
            int j = tid * 8 + e;
            double ratio = 1.0;
            if (j > 0) ratio = which ? (double)(2 * j) / (double)(2 * j + 1)
                                     : (double)(2 * j - 1) / (double)(2 * j);
            run *= ratio;
            tab[j] = (float)run;
        }
        return;
    }

    const int h0 = hb * 128;
    const int b0 = bb * 64;
    const int hg = tid >> 3;             // owns 4 h
    const int kg = tid & 7;              // owns 4 k

    if (bb == 0 && hb == 0 && tid == 0) { g_acc = 0ULL; g_done = 0u; }

    // prefetch both tiles' global data into registers (10 LDG.128)
    float4 hv[2][4], cvv[2];
    const int rH = tid >> 5;
    const int cH = tid & 31;
    const int rC = tid >> 3, cC = tid & 7;
#pragma unroll
    for (int t = 0; t < 2; t++) {
#pragma unroll
        for (int it = 0; it < 4; it++) {
            int r = rH + it * 8;
            hv[t][it] = *(const float4*)&hidden[(b0 + t * 32 + r) * HSZ + h0 + cH * 4];
        }
        cvv[t] = *(const float4*)&cluster[(b0 + t * 32 + rC) * KSZ + cC * 4];
    }

    u64 acc[4][4];
#pragma unroll
    for (int i = 0; i < 4; i++)
#pragma unroll
        for (int j = 0; j < 4; j++) acc[i][j] = 0ULL;

#pragma unroll
    for (int t = 0; t < 2; t++) {
        __syncthreads();
#pragma unroll
        for (int it = 0; it < 4; it++) {
            int r = rH + it * 8;
            float4 v = hv[t][it];
            float4 w0 = make_float4(v.x, v.x * v.x, v.y, v.y * v.y);
            float4 w1 = make_float4(v.z, v.z * v.z, v.w, v.w * v.w);
            *(float4*)&sh_hidp[r][cH * 8] = w0;
            *(float4*)&sh_hidp[r][cH * 8 + 4] = w1;
        }
        {
            float4 v = cvv[t];
            float4 w0 = make_float4(v.x, v.x * v.x, v.y, v.y * v.y);
            float4 w1 = make_float4(v.z, v.z * v.z, v.w, v.w * v.w);
            *(float4*)&sh_cp[rC][cC * 8] = w0;
            *(float4*)&sh_cp[rC][cC * 8 + 4] = w1;
        }
        __syncthreads();
#pragma unroll 4
        for (int r = 0; r < 32; r++) {
            F4U qh0, qh1, qc0, qc1;
            qh0.f = *(const float4*)&sh_hidp[r][hg * 8];
            qh1.f = *(const float4*)&sh_hidp[r][hg * 8 + 4];
            qc0.f = *(const float4*)&sh_cp[r][kg * 8];
            qc1.f = *(const float4*)&sh_cp[r][kg * 8 + 4];
            u64 hp[4] = { qh0.d[0], qh0.d[1], qh1.d[0], qh1.d[1] };
            u64 cpk[4] = { qc0.d[0], qc0.d[1], qc1.d[0], qc1.d[1] };
#pragma unroll
            for (int i = 0; i < 4; i++)
#pragma unroll
                for (int j = 0; j < 4; j++)
                    acc[i][j] = ffma2(hp[i], cpk[j], acc[i][j]);
        }
    }
#pragma unroll
    for (int i = 0; i < 4; i++) {
        int h = h0 + hg * 4 + i;
        *(float4*)&g_pm[bb][h][kg * 4] = make_float4(f2lo(acc[i][0]), f2lo(acc[i][1]), f2lo(acc[i][2]), f2lo(acc[i][3]));
        *(float4*)&g_ps[bb][h][kg * 4] = make_float4(f2hi(acc[i][0]), f2hi(acc[i][1]), f2hi(acc[i][2]), f2hi(acc[i][3]));
    }

    if (hb == 0) {
        const int k = tid & 31;
        const int seg = tid >> 5;
        double s = 0.0;
#pragma unroll
        for (int r = seg; r < 64; r += 8)
            s += (double)cluster[(b0 + r) * KSZ + k];
        __syncthreads();
        sh_cnt[tid] = s;
        __syncthreads();
        if (tid < 128) sh_cnt[tid] += sh_cnt[tid + 128];
        __syncthreads();
        if (tid < 64) sh_cnt[tid] += sh_cnt[tid + 64];
        __syncthreads();
        if (tid < 32) g_pcnt[bb][tid] = sh_cnt[tid] + sh_cnt[tid + 32];
    }
}

// ====== K2: high-occupancy reduce + meta | barrier | 1 pair/block ==========
struct Meta { float ci, cj, bf, thresh; double bd, lbeta; int nu, odd; };

__global__ __launch_bounds__(TPB, 4) void pairs_kernel(float* __restrict__ out) {
    __shared__ float sx[320];
    __shared__ float s_sel[DSZ];
    __shared__ Meta s_meta;
    __shared__ unsigned long long s_acc;

    const int tid = (int)threadIdx.x;
    const int lane = tid & 31, warp = tid >> 5;
    const int bid = (int)blockIdx.x;
    const bool has_pair = (bid < NPAIR);

    if (tid == 0) s_acc = 0ULL;

    // ----- Phase 2: m/w reduce, 8 threads/cell over 592x256 threads -----
    {
        int gt = bid * TPB + tid;          // 0..151551
        if (gt < 8 * KSZ * HSZ) {          // 131072
            int cell = gt >> 3;
            int q = gt & 7;
            int k = cell & 31;
            int h = cell >> 5;
            int p0 = q * 8;
            float smm = 0.f, ss = 0.f;
#pragma unroll
            for (int p = 0; p < 8; p++) {
                smm += g_pm[p0 + p][h][k];
                ss  += g_ps[p0 + p][h][k];
            }
            // deterministic 8-way tree combine
            smm += __shfl_xor_sync(0xffffffffu, smm, 1);
            ss  += __shfl_xor_sync(0xffffffffu, ss, 1);
            smm += __shfl_xor_sync(0xffffffffu, smm, 2);
            ss  += __shfl_xor_sync(0xffffffffu, ss, 2);
            smm += __shfl_xor_sync(0xffffffffu, smm, 4);
            ss  += __shfl_xor_sync(0xffffffffu, ss, 4);
            if (q == 0) {
                g_m[k][h] = smm;
                g_w[k][h] = ss + (float)(BSZ - 2) * smm * smm;
            }
        }
    }

    // ----- lane-parallel counts + meta (warp 0) -----
    int ii, jj;
    if (has_pair) {
        pair_ij(bid, ii, jj);
        if (warp == 0) {
            double si = g_pcnt[lane][ii] + g_pcnt[lane + 32][ii];
            double sj = g_pcnt[lane][jj] + g_pcnt[lane + 32][jj];
#pragma unroll
            for (int off = 16; off; off >>= 1) {
                si += __shfl_xor_sync(0xffffffffu, si, off);
                sj += __shfl_xor_sync(0xffffffffu, sj, off);
            }
            if (lane == 0) {
                float ci = (float)rint(si), cj = (float)rint(sj);
                float d2 = (ci + cj) - 2.0f;
                if (d2 == 0.0f) d2 += 1e-5f;
                double bd = 0.5 * (double)d2;
                bool isint = (d2 == rintf(d2)) && (d2 >= 1.0f) && (d2 <= 4094.0f);
                Meta mt;
                mt.ci = ci; mt.cj = cj;
                mt.bf = (float)bd;
                mt.thresh = 1.5f / ((float)bd + 2.5f);
                mt.bd = bd;
                mt.nu = isint ? (int)d2 : 0;
                mt.odd = ((int)d2) & 1;
                mt.lbeta = isint ? 0.0 : lbeta_half(bd);
                s_meta = mt;
            }
        }
    }

    grid_barrier();

    if (has_pair) {
        // ----- x + bitonic top-20s per warp-half -----
        float ci = s_meta.ci, cj = s_meta.cj;
#pragma unroll
        for (int half = 0; half < 2; half++) {
            int h = tid + half * 256;
            float mi = g_m[ii][h], mj = g_m[jj][h];
            float wi = g_w[ii][h], wj = g_w[jj][h];
            float gmv = 0.5f * (mi + mj);
            float di = mi - gmv, dj = mj - gmv;
            float between = di * di * ci + dj * dj * cj;
            float x = between / (between + wi + wj);
            x = fminf(fmaxf(x, 1e-37f), 1.0f - 1e-5f);
            float v = x;
#pragma unroll
            for (int kk = 2; kk <= 32; kk <<= 1)
#pragma unroll
                for (int js = kk >> 1; js > 0; js >>= 1) {
                    float o = __shfl_xor_sync(0xffffffffu, v, js);
                    bool up = ((lane & kk) == 0);
                    bool lo = ((lane & js) == 0);
                    v = (up == lo) ? fmaxf(v, o) : fminf(v, o);
                }
            if (lane < DSZ) sx[warp * 40 + half * DSZ + lane] = v;
        }
        __syncthreads();

        // ----- serial merge (warp 0), ballot-claim -----
        if (warp == 0) {
            float r[10];
#pragma unroll
            for (int qq = 0; qq < 10; qq++) r[qq] = sx[lane * 10 + qq];
#pragma unroll
            for (int a = 0; a < 10; a++)
#pragma unroll
                for (int bq = 0; bq < 9 - a; bq++) {
                    float x0 = r[bq], x1 = r[bq + 1];
                    r[bq] = fmaxf(x0, x1); r[bq + 1] = fminf(x0, x1);
                }
            int ptr = 0;
            float head = r[0];
#pragma unroll 1
            for (int t = 0; t < DSZ; t++) {
                float mx = head;
#pragma unroll
                for (int off = 16; off; off >>= 1)
                    mx = fmaxf(mx, __shfl_xor_sync(0xffffffffu, mx, off));
                unsigned msk = __ballot_sync(0xffffffffu, head == mx);
                int wl = __ffs(msk) - 1;
                if (lane == wl) {
                    ptr++;
                    float nh = -1e38f;
#pragma unroll
                    for (int qq = 1; qq < 10; qq++) nh = (ptr == qq) ? r[qq] : nh;
                    head = nh;
                }
                if (lane == 0) s_sel[t] = mx;
            }
        }
        __syncthreads();

        // ----- warp-parallel exact Student-t series; 8 warps over 20 values --
        Meta mt = s_meta;
        for (int t = warp; t < DSZ; t += 8) {
            float xx = s_sel[t];
            float uu = 1.0f - xx;
            if (mt.nu > 0) {
                int n = mt.odd ? ((mt.nu - 1) >> 1) : (mt.nu >> 1);
                const float* tab = mt.odd ? g_tab_odd : g_tab_even;
                float u1 = uu, u2 = u1 * u1, u4 = u2 * u2, u8 = u4 * u4, u16 = u8 * u8;
                float pw = 1.0f;
                if (lane & 1)  pw *= u1;
                if (lane & 2)  pw *= u2;
                if (lane & 4)  pw *= u4;
                if (lane & 8)  pw *= u8;
                if (lane & 16) pw *= u16;
                float u32f = u16 * u16;
                float sum = 0.0f;
#pragma unroll 1
                for (int j0 = 0; j0 < n; j0 += 32) {
                    int j = j0 + lane;
                    float cj2 = (j < n) ? __ldg(&tab[j]) : 0.0f;
                    sum = fmaf(cj2, pw, sum);
                    pw *= u32f;
                }
#pragma unroll
                for (int off = 16; off; off >>= 1)
                    sum += __shfl_xor_sync(0xffffffffu, sum, off);
                if (lane == 0) {
                    float I;
                    if (mt.odd) {
                        float s = sqrtf(xx), su = sqrtf(uu);
                        I = 0.63661977236758134f * (asinf(s) + s * su * sum);
                    } else {
                        I = sqrtf(xx) * sum;
                    }
                    double logI = (double)logf(fminf(I, 1.0f));
                    long long fx = __double2ll_rn(logI * 4294967296.0);
                    atomicAdd(&s_acc, (unsigned long long)fx);
                }
            } else if (lane == 0) {
                float bf = mt.bf;
                bool sel = xx < mt.thresh;
                float pa = sel ? 0.5f : bf;
                float pb = sel ? bf : 0.5f;
                float px = sel ? xx : uu;
                float cf = betacf_thread(pa, pb, px);
                double lbt = 0.5 * (double)logf(xx) + mt.bd * (double)log1pf(-xx) - mt.lbeta;
                double logI;
                if (sel) logI = lbt + (double)logf(2.0f * cf);
                else {
                    double T = exp(lbt + (double)logf(cf / bf));
                    logI = (double)log1pf(-(float)T);
                }
                long long fx = __double2ll_rn(logI * 4294967296.0);
                atomicAdd(&s_acc, (unsigned long long)fx);
            }
        }
        __syncthreads();
    }

    if (tid == 0) {
        if (has_pair) atomicAdd(&g_acc, s_acc);
        __threadfence();
        unsigned int t = atomicAdd(&g_done, 1u);
        if (t == GRID - 1) {
            long long total = (long long)atomicAdd(&g_acc, 0ULL);
            out[0] = (float)(-(double)total * (1.0 / 4294967296.0));
        }
    }
}

extern "C" void kernel_launch(void* const* d_in, const int* in_sizes, int n_in,
                              void* d_out, int out_size) {
    (void)in_sizes; (void)n_in; (void)out_size;
    const float* hidden  = (const float*)d_in[0];
    const float* cluster = (const float*)d_in[1];
    float* out = (float*)d_out;

    dim3 gA(NBB + 2, 4);
    stats_kernel<<<gA, TPB>>>(hidden, cluster);
    pairs_kernel<<<GRID, TPB>>>(out);
}

// round 15
// speedup vs baseline: 1.0147x; 1.0147x over previous
#include <cuda_runtime.h>
#include <math.h>

#define BSZ 4096
#define HSZ 512
#define KSZ 32
#define DSZ 20
#define NPAIR 496   // 32*31/2
#define NBB 64
#define TPB 256

typedef unsigned long long u64;

// ---------------- device scratch (no allocations allowed) ----------------
__device__ float  g_pm[NBB][HSZ][KSZ];   // partial class sums  [bb][h][k]
__device__ float  g_ps[NBB][HSZ][KSZ];   // partial sum h^2c^2  [bb][h][k]
__device__ double g_pcnt[NBB][KSZ];
__device__ float  g_m[KSZ][HSZ];
__device__ float  g_w[KSZ][HSZ];
__device__ float  g_tab_even[2048];      // c_j = (2j-1)!!/(2j)!!
__device__ float  g_tab_odd[2048];       // c_j = (2j)!!/(2j+1)!!

__device__ volatile unsigned int g_kflag[4];   // per-k-group ready flags
__device__ unsigned int g_kcnt[4];             // per-group producer counters

__device__ unsigned long long g_acc;     // fixed-point (2^-32) accumulator
__device__ unsigned int g_done;

__device__ __forceinline__ u64 ffma2(u64 a, u64 b, u64 c) {
    u64 d;
    asm("fma.rn.f32x2 %0, %1, %2, %3;" : "=l"(d) : "l"(a), "l"(b), "l"(c));
    return d;
}
__device__ __forceinline__ float f2lo(u64 v) { return __uint_as_float((unsigned)v); }
__device__ __forceinline__ float f2hi(u64 v) { return __uint_as_float((unsigned)(v >> 32)); }

union F4U { float4 f; u64 d[2]; };

// ln B(1/2, b) without lgamma (CF fallback path only).
__device__ __forceinline__ double lbeta_half(double b) {
    double z = b, prod = 1.0;
#pragma unroll 1
    while (z < 32.0) { prod *= z / (z + 0.5); z += 1.0; }
    double iz = 1.0 / z;
    double ser = 1.0 + iz * (-0.125 + iz * (0.0078125 +
                 iz * (0.0048828125 + iz * (-0.000640869140625))));
    return 0.57236494292470008707 - log(prod * sqrt(z) * ser);
}

// Per-thread Lentz CF (divergence-safe). Fallback only (non-integer nu).
__device__ __forceinline__ float betacf_thread(float a, float b, float x) {
    const float FPMIN = 1e-30f;
    float qab = a + b, qap = a + 1.0f, qam = a - 1.0f;
    float c = 1.0f;
    float d = 1.0f - qab * x / qap;
    if (fabsf(d) < FPMIN) d = FPMIN;
    d = 1.0f / d;
    float hh = d;
#pragma unroll 1
    for (int m = 1; m <= 200; m++) {
        float fm = (float)m, m2 = 2.0f * fm;
        float aa = fm * (b - fm) * x / ((qam + m2) * (a + m2));
        d = 1.0f + aa * d; if (fabsf(d) < FPMIN) d = FPMIN;
        c = 1.0f + aa / c; if (fabsf(c) < FPMIN) c = FPMIN;
        d = 1.0f / d;
        hh *= d * c;
        aa = -(a + fm) * (qab + fm) * x / ((a + m2) * (qap + m2));
        d = 1.0f + aa * d; if (fabsf(d) < FPMIN) d = FPMIN;
        c = 1.0f + aa / c; if (fabsf(c) < FPMIN) c = FPMIN;
        d = 1.0f / d;
        float del = d * c;
        hh *= del;
        if (fabsf(del - 1.0f) < 2.4e-7f) break;
    }
    return hh;
}

__device__ __forceinline__ void pair_ij(int p, int& ii, int& jj) {
    int i = 0, rem = p;
    while (rem >= (KSZ - 1 - i)) { rem -= (KSZ - 1 - i); i++; }
    ii = i; jj = i + 1 + rem;
}

// ====== K1: stats (grid (66,4)); bb 64/65 build coeff tables ==============
__global__ __launch_bounds__(TPB) void stats_kernel(const float* __restrict__ hidden,
                                                    const float* __restrict__ cluster) {
    __shared__ float sh_hidp[32][256];   // packed pairs {h, h^2}
    __shared__ float sh_cp[32][64];      // packed pairs {c, c^2}
    __shared__ double sh_cnt[TPB];

    const int tid = (int)threadIdx.x;
    const int bb = (int)blockIdx.x;
    const int hb = (int)blockIdx.y;

    if (bb >= NBB) {
        if (hb != 0) return;
        const int which = bb - NBB;      // 0 = even, 1 = odd
        __shared__ double sp[TPB];
        double prod = 1.0;
#pragma unroll
        for (int e = 0; e < 8; e++) {
            int j = tid * 8 + e;
            double ratio = 1.0;
            if (j > 0) ratio = which ? (double)(2 * j) / (double)(2 * j + 1)
                                     : (double)(2 * j - 1) / (double)(2 * j);
            prod *= ratio;
        }
        sp[tid] = prod;
        __syncthreads();
        for (int off = 1; off < TPB; off <<= 1) {
            double v = sp[tid];
            double u = (tid >= off) ? sp[tid - off] : 1.0;
            __syncthreads();
            sp[tid] = v * u;
            __syncthreads();
        }
        double run = (tid == 0) ? 1.0 : sp[tid - 1];
        float* tab = which ? g_tab_odd : g_tab_even;
#pragma unroll
        for (int e = 0; e < 8; e++) {
            int j = tid * 8 + e;
            double ratio = 1.0;
            if (j > 0) ratio = which ? (double)(2 * j) / (double)(2 * j + 1)
                                     : (double)(2 * j - 1) / (double)(2 * j);
            run *= ratio;
            tab[j] = (float)run;
        }
        return;
    }

    const int h0 = hb * 128;
    const int b0 = bb * 64;
    const int hg = tid >> 3;             // owns 4 h
    const int kg = tid & 7;              // owns 4 k

    if (bb == 0 && hb == 0 && tid < 8) {
        if (tid == 0) { g_acc = 0ULL; g_done = 0u; }
        if (tid < 4) { g_kflag[tid] = 0u; g_kcnt[tid] = 0u; }
    }

    // prefetch both tiles' global data into registers (10 LDG.128)
    float4 hv[2][4], cvv[2];
    const int rH = tid >> 5;
    const int cH = tid & 31;
    const int rC = tid >> 3, cC = tid & 7;
#pragma unroll
    for (int t = 0; t < 2; t++) {
#pragma unroll
        for (int it = 0; it < 4; it++) {
            int r = rH + it * 8;
            hv[t][it] = *(const float4*)&hidden[(b0 + t * 32 + r) * HSZ + h0 + cH * 4];
        }
        cvv[t] = *(const float4*)&cluster[(b0 + t * 32 + rC) * KSZ + cC * 4];
    }

    u64 acc[4][4];
#pragma unroll
    for (int i = 0; i < 4; i++)
#pragma unroll
        for (int j = 0; j < 4; j++) acc[i][j] = 0ULL;

#pragma unroll
    for (int t = 0; t < 2; t++) {
        __syncthreads();
#pragma unroll
        for (int it = 0; it < 4; it++) {
            int r = rH + it * 8;
            float4 v = hv[t][it];
            float4 w0 = make_float4(v.x, v.x * v.x, v.y, v.y * v.y);
            float4 w1 = make_float4(v.z, v.z * v.z, v.w, v.w * v.w);
            *(float4*)&sh_hidp[r][cH * 8] = w0;
            *(float4*)&sh_hidp[r][cH * 8 + 4] = w1;
        }
        {
            float4 v = cvv[t];
            float4 w0 = make_float4(v.x, v.x * v.x, v.y, v.y * v.y);
            float4 w1 = make_float4(v.z, v.z * v.z, v.w, v.w * v.w);
            *(float4*)&sh_cp[rC][cC * 8] = w0;
            *(float4*)&sh_cp[rC][cC * 8 + 4] = w1;
        }
        __syncthreads();
#pragma unroll 4
        for (int r = 0; r < 32; r++) {
            F4U qh0, qh1, qc0, qc1;
            qh0.f = *(const float4*)&sh_hidp[r][hg * 8];
            qh1.f = *(const float4*)&sh_hidp[r][hg * 8 + 4];
            qc0.f = *(const float4*)&sh_cp[r][kg * 8];
            qc1.f = *(const float4*)&sh_cp[r][kg * 8 + 4];
            u64 hp[4] = { qh0.d[0], qh0.d[1], qh1.d[0], qh1.d[1] };
            u64 cpk[4] = { qc0.d[0], qc0.d[1], qc1.d[0], qc1.d[1] };
#pragma unroll
            for (int i = 0; i < 4; i++)
#pragma unroll
                for (int j = 0; j < 4; j++)
                    acc[i][j] = ffma2(hp[i], cpk[j], acc[i][j]);
        }
    }
#pragma unroll
    for (int i = 0; i < 4; i++) {
        int h = h0 + hg * 4 + i;
        *(float4*)&g_pm[bb][h][kg * 4] = make_float4(f2lo(acc[i][0]), f2lo(acc[i][1]), f2lo(acc[i][2]), f2lo(acc[i][3]));
        *(float4*)&g_ps[bb][h][kg * 4] = make_float4(f2hi(acc[i][0]), f2hi(acc[i][1]), f2hi(acc[i][2]), f2hi(acc[i][3]));
    }

    if (hb == 0) {
        const int k = tid & 31;
        const int seg = tid >> 5;
        double s = 0.0;
#pragma unroll
        for (int r = seg; r < 64; r += 8)
            s += (double)cluster[(b0 + r) * KSZ + k];
        __syncthreads();
        sh_cnt[tid] = s;
        __syncthreads();
        if (tid < 128) sh_cnt[tid] += sh_cnt[tid + 128];
        __syncthreads();
        if (tid < 64) sh_cnt[tid] += sh_cnt[tid + 64];
        __syncthreads();
        if (tid < 32) g_pcnt[bb][tid] = sh_cnt[tid] + sh_cnt[tid + 32];
    }
}

// ====== K2: 496 blocks, 1 pair each; blocks 0..127 also produce m/w ========
struct Meta { float ci, cj, bf, thresh; double bd, lbeta; int nu, odd; };

__global__ __launch_bounds__(TPB, 4) void pairs_kernel(float* __restrict__ out) {
    __shared__ float sx[320];
    __shared__ float s_sel[DSZ];
    __shared__ Meta s_meta;
    __shared__ unsigned long long s_acc;

    const int tid = (int)threadIdx.x;
    const int lane = tid & 31, warp = tid >> 5;
    const int bid = (int)blockIdx.x;

    if (tid == 0) s_acc = 0ULL;

    int ii, jj;
    pair_ij(bid, ii, jj);

    // ----- producer slice: blocks 0..127 reduce one (k-group, h-slice) -----
    if (bid < 128) {
        const int g = bid & 3;             // k-group: k in [8g, 8g+8)
        const int hs = bid >> 2;           // h-slice: h in [16hs, 16hs+16)
        int cell = tid >> 1;               // 0..127 = 16h x 8k
        int half = tid & 1;
        int k = g * 8 + (cell & 7);
        int h = hs * 16 + (cell >> 3);
        int p0 = half * 32;
        float smm = 0.f, ss = 0.f;
#pragma unroll
        for (int p = 0; p < 32; p++) {
            smm += g_pm[p0 + p][h][k];
            ss  += g_ps[p0 + p][h][k];
        }
        smm += __shfl_xor_sync(0xffffffffu, smm, 1);
        ss  += __shfl_xor_sync(0xffffffffu, ss, 1);
        if (half == 0) {
            g_m[k][h] = smm;
            g_w[k][h] = ss + (float)(BSZ - 2) * smm * smm;
        }
        __syncthreads();
        __threadfence();
        if (tid == 0) {
            unsigned r = atomicAdd(&g_kcnt[g], 1u);
            if (r == 31u) g_kflag[g] = 1u;   // release: fence above covers chain
        }
    }

    // ----- lane-parallel counts + meta (warp 0), independent of flags -----
    if (warp == 0) {
        double si = g_pcnt[lane][ii] + g_pcnt[lane + 32][ii];
        double sj = g_pcnt[lane][jj] + g_pcnt[lane + 32][jj];
#pragma unroll
        for (int off = 16; off; off >>= 1) {
            si += __shfl_xor_sync(0xffffffffu, si, off);
            sj += __shfl_xor_sync(0xffffffffu, sj, off);
        }
        if (lane == 0) {
            float ci = (float)rint(si), cj = (float)rint(sj);
            float d2 = (ci + cj) - 2.0f;
            if (d2 == 0.0f) d2 += 1e-5f;
            double bd = 0.5 * (double)d2;
            bool isint = (d2 == rintf(d2)) && (d2 >= 1.0f) && (d2 <= 4094.0f);
            Meta mt;
            mt.ci = ci; mt.cj = cj;
            mt.bf = (float)bd;
            mt.thresh = 1.5f / ((float)bd + 2.5f);
            mt.bd = bd;
            mt.nu = isint ? (int)d2 : 0;
            mt.odd = ((int)d2) & 1;
            mt.lbeta = isint ? 0.0 : lbeta_half(bd);
            s_meta = mt;
        }
    }

    // ----- wait only for the two k-groups this pair needs -----
    if (tid == 0) {
        int gi = ii >> 3, gj = jj >> 3;
        while (g_kflag[gi] == 0u) __nanosleep(32);
        while (g_kflag[gj] == 0u) __nanosleep(32);
        __threadfence();   // acquire
    }
    __syncthreads();

    // ----- x + bitonic top-20s per warp-half -----
    {
        float ci = s_meta.ci, cj = s_meta.cj;
#pragma unroll
        for (int half = 0; half < 2; half++) {
            int h = tid + half * 256;
            float mi = g_m[ii][h], mj = g_m[jj][h];
            float wi = g_w[ii][h], wj = g_w[jj][h];
            float gmv = 0.5f * (mi + mj);
            float di = mi - gmv, dj = mj - gmv;
            float between = di * di * ci + dj * dj * cj;
            float x = between / (between + wi + wj);
            x = fminf(fmaxf(x, 1e-37f), 1.0f - 1e-5f);
            float v = x;
#pragma unroll
            for (int kk = 2; kk <= 32; kk <<= 1)
#pragma unroll
                for (int js = kk >> 1; js > 0; js >>= 1) {
                    float o = __shfl_xor_sync(0xffffffffu, v, js);
                    bool up = ((lane & kk) == 0);
                    bool lo = ((lane & js) == 0);
                    v = (up == lo) ? fmaxf(v, o) : fminf(v, o);
                }
            if (lane < DSZ) sx[warp * 40 + half * DSZ + lane] = v;
        }
    }
    __syncthreads();

    // ----- serial merge (warp 0), ballot-claim -----
    if (warp == 0) {
        float r[10];
#pragma unroll
        for (int qq = 0; qq < 10; qq++) r[qq] = sx[lane * 10 + qq];
#pragma unroll
        for (int a = 0; a < 10; a++)
#pragma unroll
            for (int bq = 0; bq < 9 - a; bq++) {
                float x0 = r[bq], x1 = r[bq + 1];
                r[bq] = fmaxf(x0, x1); r[bq + 1] = fminf(x0, x1);
            }
        int ptr = 0;
        float head = r[0];
#pragma unroll 1
        for (int t = 0; t < DSZ; t++) {
            float mx = head;
#pragma unroll
            for (int off = 16; off; off >>= 1)
                mx = fmaxf(mx, __shfl_xor_sync(0xffffffffu, mx, off));
            unsigned msk = __ballot_sync(0xffffffffu, head == mx);
            int wl = __ffs(msk) - 1;
            if (lane == wl) {
                ptr++;
                float nh = -1e38f;
#pragma unroll
                for (int qq = 1; qq < 10; qq++) nh = (ptr == qq) ? r[qq] : nh;
                head = nh;
            }
            if (lane == 0) s_sel[t] = mx;
        }
    }
    __syncthreads();

    // ----- warp-parallel exact Student-t series; 8 warps over 20 values -----
    {
        Meta mt = s_meta;
        for (int t = warp; t < DSZ; t += 8) {
            float xx = s_sel[t];
            float uu = 1.0f - xx;
            if (mt.nu > 0) {
                int n = mt.odd ? ((mt.nu - 1) >> 1) : (mt.nu >> 1);
                const float* tab = mt.odd ? g_tab_odd : g_tab_even;
                float u1 = uu, u2 = u1 * u1, u4 = u2 * u2, u8 = u4 * u4, u16 = u8 * u8;
                float pw = 1.0f;
                if (lane & 1)  pw *= u1;
                if (lane & 2)  pw *= u2;
                if (lane & 4)  pw *= u4;
                if (lane & 8)  pw *= u8;
                if (lane & 16) pw *= u16;
                float u32f = u16 * u16;
                float sum = 0.0f;
#pragma unroll 1
                for (int j0 = 0; j0 < n; j0 += 32) {
                    int j = j0 + lane;
                    float cj2 = (j < n) ? __ldg(&tab[j]) : 0.0f;
                    sum = fmaf(cj2, pw, sum);
                    pw *= u32f;
                }
#pragma unroll
                for (int off = 16; off; off >>= 1)
                    sum += __shfl_xor_sync(0xffffffffu, sum, off);
                if (lane == 0) {
                    float I;
                    if (mt.odd) {
                        float s = sqrtf(xx), su = sqrtf(uu);
                        I = 0.63661977236758134f * (asinf(s) + s * su * sum);
                    } else {
                        I = sqrtf(xx) * sum;
                    }
                    double logI = (double)logf(fminf(I, 1.0f));
                    long long fx = __double2ll_rn(logI * 4294967296.0);
                    atomicAdd(&s_acc, (unsigned long long)fx);
                }
            } else if (lane == 0) {
                float bf = mt.bf;
                bool sel = xx < mt.thresh;
                float pa = sel ? 0.5f : bf;
                float pb = sel ? bf : 0.5f;
                float px = sel ? xx : uu;
                float cf = betacf_thread(pa, pb, px);
                double lbt = 0.5 * (double)logf(xx) + mt.bd * (double)log1pf(-xx) - mt.lbeta;
                double logI;
                if (sel) logI = lbt + (double)logf(2.0f * cf);
                else {
                    double T = exp(lbt + (double)logf(cf / bf));
                    logI = (double)log1pf(-(float)T);
                }
                long long fx = __double2ll_rn(logI * 4294967296.0);
                atomicAdd(&s_acc, (unsigned long long)fx);
            }
        }
    }
    __syncthreads();

    if (tid == 0) {
        atomicAdd(&g_acc, s_acc);
        __threadfence();
        unsigned int t = atomicAdd(&g_done, 1u);
        if (t == NPAIR - 1) {
            long long total = (long long)atomicAdd(&g_acc, 0ULL);
            out[0] = (float)(-(double)total * (1.0 / 4294967296.0));
        }
    }
}

extern "C" void kernel_launch(void* const* d_in, const int* in_sizes, int n_in,
                              void* d_out, int out_size) {
    (void)in_sizes; (void)n_in; (void)out_size;
    const float* hidden  = (const float*)d_in[0];
    const float* cluster = (const float*)d_in[1];
    float* out = (float*)d_out;

    dim3 gA(NBB + 2, 4);
    stats_kernel<<<gA, TPB>>>(hidden, cluster);
    pairs_kernel<<<NPAIR, TPB>>>(out);
}